// round 9
// baseline (speedup 1.0000x reference)
#include <cuda_runtime.h>
#include <cuda_fp16.h>
#include <math.h>
#include <stdint.h>

// Problem constants
#define BATCH   4
#define NSEQ    2048
#define DIM     1024
#define NHEAD   16
#define HD      64
#define M_ROWS  (BATCH * NSEQ)      // 8192
#define QKV_N   (3 * DIM)           // 3072

// ---------------------------------------------------------------------------
// Scratch (device globals: allocation-free per harness rules)
// ---------------------------------------------------------------------------
__device__ __half g_x_h[M_ROWS * DIM];       // x in fp16
__device__ __half g_qkv_h[M_ROWS * QKV_N];   // qkv in fp16
__device__ __half g_att_h[M_ROWS * DIM];     // attention out in fp16
__device__ __half g_wqkv_h[QKV_N * DIM];     // W_qkv^T  [3072,1024] fp16
__device__ __half g_wproj_h[DIM * DIM];      // W_proj^T [1024,1024] fp16

// ---------------------------------------------------------------------------
// Helpers
// ---------------------------------------------------------------------------
__device__ __forceinline__ uint32_t smem_u32(const void* p) {
    uint32_t a;
    asm("{ .reg .u64 t; cvta.to.shared.u64 t, %1; cvt.u32.u64 %0, t; }"
        : "=r"(a) : "l"(p));
    return a;
}

__device__ __forceinline__ void cp_async16(uint32_t dst, const void* src) {
    asm volatile("cp.async.cg.shared.global [%0], [%1], 16;" :: "r"(dst), "l"(src));
}
__device__ __forceinline__ void cp_commit() {
    asm volatile("cp.async.commit_group;" ::: "memory");
}
__device__ __forceinline__ void cp_wait0() {
    asm volatile("cp.async.wait_group 0;" ::: "memory");
}
__device__ __forceinline__ void cp_wait1() {
    asm volatile("cp.async.wait_group 1;" ::: "memory");
}

__device__ __forceinline__ void ldsm_x4(unsigned* r, uint32_t addr) {
    asm volatile("ldmatrix.sync.aligned.m8n8.x4.shared.b16 {%0,%1,%2,%3}, [%4];"
                 : "=r"(r[0]), "=r"(r[1]), "=r"(r[2]), "=r"(r[3]) : "r"(addr));
}
__device__ __forceinline__ void ldsm_x4_t(unsigned* r, uint32_t addr) {
    asm volatile("ldmatrix.sync.aligned.m8n8.x4.trans.shared.b16 {%0,%1,%2,%3}, [%4];"
                 : "=r"(r[0]), "=r"(r[1]), "=r"(r[2]), "=r"(r[3]) : "r"(addr));
}

// mma m16n8k16 fp16 -> fp32
__device__ __forceinline__ void mma_f16(float* c,
                                        unsigned a0, unsigned a1, unsigned a2, unsigned a3,
                                        unsigned b0, unsigned b1) {
    asm volatile(
        "mma.sync.aligned.m16n8k16.row.col.f32.f16.f16.f32 "
        "{%0,%1,%2,%3},{%4,%5,%6,%7},{%8,%9},{%0,%1,%2,%3};"
        : "+f"(c[0]), "+f"(c[1]), "+f"(c[2]), "+f"(c[3])
        : "r"(a0), "r"(a1), "r"(a2), "r"(a3), "r"(b0), "r"(b1));
}

// pack (lo, hi) f32 -> f16x2, then 2^x elementwise
__device__ __forceinline__ unsigned ex2_f16x2(float lo, float hi) {
    unsigned r;
    asm("{ .reg .b32 t; cvt.rn.f16x2.f32 t, %2, %1; ex2.approx.f16x2 %0, t; }"
        : "=r"(r) : "f"(lo), "f"(hi));
    return r;
}

// ---------------------------------------------------------------------------
// f32 -> f16 convert
// ---------------------------------------------------------------------------
__global__ void f32_to_f16_kernel(const float* __restrict__ in, __half* __restrict__ outp, int n)
{
    int i = (blockIdx.x * blockDim.x + threadIdx.x) * 4;
    if (i < n) {
        float4 v = *(const float4*)(in + i);
        *(__half2*)(outp + i)     = __floats2half2_rn(v.x, v.y);
        *(__half2*)(outp + i + 2) = __floats2half2_rn(v.z, v.w);
    }
}

// ---------------------------------------------------------------------------
// Transpose + convert: out_h[c][r] = (half) in[r][c]
// ---------------------------------------------------------------------------
__global__ void transpose_cvt_kernel(const float* __restrict__ in, __half* __restrict__ outp,
                                     int R, int C)
{
    __shared__ float t[32][33];
    const int c0 = blockIdx.x * 32;
    const int r0 = blockIdx.y * 32;
    for (int i = threadIdx.y; i < 32; i += 8)
        t[i][threadIdx.x] = in[(size_t)(r0 + i) * C + c0 + threadIdx.x];
    __syncthreads();
    for (int i = threadIdx.y; i < 32; i += 8)
        outp[(size_t)(c0 + i) * R + r0 + threadIdx.x] = __float2half(t[threadIdx.x][i]);
}

// ---------------------------------------------------------------------------
// HGEMM v2: C[M,N] = A[M,K] @ Bt^T + bias.  BK=64 halves (128 B rows),
// 128x128 tile, 256 threads (8 warps 2x4), warp tile 64x32, 3-stage cp.async.
// smem rows: 8 chunks of 16B, chunk c stored at c ^ (row & 7).
// ---------------------------------------------------------------------------
#define TS 3
#define OPB 16384                     // 128 rows * 128 B
#define STAGEB (2 * OPB)
#define GEMM_SMEM (TS * STAGEB)       // 98304

template <bool OUT_HALF>
__global__ __launch_bounds__(256, 2)
void hgemm_kernel(const __half* __restrict__ A,
                  const __half* __restrict__ Bt,
                  const float* __restrict__ bias,
                  void* __restrict__ Cv,
                  int M, int N, int K)
{
    extern __shared__ __align__(16) unsigned char dsm[];
    const uint32_t smem_base = smem_u32(dsm);

    const int tid  = threadIdx.x;
    const int warp = tid >> 5;
    const int lane = tid & 31;
    const int grp  = lane >> 2;
    const int q4   = lane & 3;

    const int wm = warp >> 2;
    const int wn = warp & 3;
    const int bx = blockIdx.x;
    const int by = blockIdx.y;

    const __half* Ag = A  + (size_t)(by * 128) * K;
    const __half* Bg = Bt + (size_t)(bx * 128) * K;
    const int NK = K / 64;

    const int rowA_base = wm * 64 + (lane & 15);
    const int hiA  = lane >> 4;
    const int rowB_base = wn * 32 + (lane & 7) + ((lane & 16) ? 8 : 0);
    const int hiB  = (lane >> 3) & 1;

    float acc[4][4][4];
#pragma unroll
    for (int mt = 0; mt < 4; mt++)
#pragma unroll
        for (int nt = 0; nt < 4; nt++)
#pragma unroll
            for (int j = 0; j < 4; j++) acc[mt][nt][j] = 0.f;

    // stage loader: 1024 16B chunks per operand, 4 per thread each
    auto load_stage = [&](int tile, int s) {
        const uint32_t base = smem_base + (uint32_t)s * STAGEB;
        const int koff = tile * 64;
#pragma unroll
        for (int j = 0; j < 4; j++) {
            const int c   = tid + 256 * j;
            const int row = c >> 3;
            const int col = c & 7;
            const uint32_t dst = base + 128u * row + 16u * (uint32_t)(col ^ (row & 7));
            cp_async16(dst,       Ag + (size_t)row * K + koff + col * 8);
            cp_async16(dst + OPB, Bg + (size_t)row * K + koff + col * 8);
        }
        cp_commit();
    };

    load_stage(0, 0);
    load_stage(1, 1);

    for (int it = 0; it < NK; it++) {
        cp_wait1();            // tile `it` resident
        __syncthreads();       // all warps done with the slot we're about to refill

        if (it + 2 < NK) load_stage(it + 2, (it + 2) % TS);
        else             cp_commit();

        const uint32_t sA = smem_base + (uint32_t)(it % TS) * STAGEB;
        const uint32_t sB = sA + OPB;

#pragma unroll
        for (int kk = 0; kk < 4; kk++) {
            unsigned af[4][4];
#pragma unroll
            for (int mt = 0; mt < 4; mt++) {
                const int r = rowA_base + mt * 16;
                ldsm_x4(af[mt], sA + 128u * r
                                   + 16u * (uint32_t)((kk * 2 + hiA) ^ (r & 7)));
            }
            unsigned bf[2][4];
#pragma unroll
            for (int ntp = 0; ntp < 2; ntp++) {
                const int r = rowB_base + ntp * 16;
                ldsm_x4(bf[ntp], sB + 128u * r
                                    + 16u * (uint32_t)((kk * 2 + hiB) ^ (r & 7)));
            }
#pragma unroll
            for (int mt = 0; mt < 4; mt++)
#pragma unroll
                for (int nt = 0; nt < 4; nt++)
                    mma_f16(acc[mt][nt],
                            af[mt][0], af[mt][1], af[mt][2], af[mt][3],
                            bf[nt >> 1][(nt & 1) * 2], bf[nt >> 1][(nt & 1) * 2 + 1]);
        }
    }

#pragma unroll
    for (int mt = 0; mt < 4; mt++) {
        const int row = by * 128 + wm * 64 + mt * 16 + grp;
#pragma unroll
        for (int nt = 0; nt < 4; nt++) {
            const int col = bx * 128 + wn * 32 + nt * 8 + 2 * q4;
            float2 bv = *(const float2*)&bias[col];
            float v0 = acc[mt][nt][0] + bv.x;
            float v1 = acc[mt][nt][1] + bv.y;
            float v2 = acc[mt][nt][2] + bv.x;
            float v3 = acc[mt][nt][3] + bv.y;
            if (OUT_HALF) {
                __half* C = (__half*)Cv;
                *(__half2*)&C[(size_t)row * N + col]       = __floats2half2_rn(v0, v1);
                *(__half2*)&C[(size_t)(row + 8) * N + col] = __floats2half2_rn(v2, v3);
            } else {
                float* C = (float*)Cv;
                float2 w0 = { v0, v1 }, w1 = { v2, v3 };
                *(float2*)&C[(size_t)row * N + col]       = w0;
                *(float2*)&C[(size_t)(row + 8) * N + col] = w1;
            }
        }
    }
}

// ---------------------------------------------------------------------------
// Flash attention v3: fp16 mma, P kept entirely in registers (S C-fragment
// == PV A-fragment identity), Q fragments hoisted out of the key loop,
// ex2.f16x2 softmax, ones-column row-sum, cp.async double-buffered K/V.
// Grid (NSEQ/64, NHEAD, BATCH), 128 threads (4 warps).
//   smem: Q [64][64]  K[2][64][64]  V[2][64][64]  (all half, 128B swizzled rows)
// ---------------------------------------------------------------------------
#define FA_TILES (NSEQ / 64)          // 32
#define FA_SMEM  (5 * 8192)           // Q + 2K + 2V = 40 KB
#define ALPHA    0.1803368801111184f  // 0.125 * log2(e)

__global__ __launch_bounds__(128)
void flash_f16_kernel(const __half* __restrict__ qkv, __half* __restrict__ outp)
{
    extern __shared__ __align__(16) unsigned char fsm[];
    const uint32_t Qb = smem_u32(fsm);
    const uint32_t Kb = Qb + 8192;        // 2 buffers
    const uint32_t Vb = Kb + 2 * 8192;    // 2 buffers

    const int tid  = threadIdx.x;
    const int w    = tid >> 5;
    const int lane = tid & 31;
    const int grp  = lane >> 2;
    const int q4   = lane & 3;

    const int q0 = blockIdx.x * 64;
    const int h  = blockIdx.y;
    const int b  = blockIdx.z;

    const __half* baseQ  = qkv + (size_t)(b * NSEQ + q0) * QKV_N + h * HD;
    const __half* baseK0 = qkv + (size_t)b * NSEQ * QKV_N + DIM + h * HD;

    auto load_kv = [&](int tile, int buf) {
        const __half* bK = baseK0 + (size_t)(tile * 64) * QKV_N;
        const __half* bV = bK + DIM;
        const uint32_t kd = Kb + (uint32_t)buf * 8192;
        const uint32_t vd = Vb + (uint32_t)buf * 8192;
#pragma unroll
        for (int j = 0; j < 4; j++) {
            const int i   = tid + 128 * j;
            const int row = i >> 3;
            const int c   = i & 7;
            const uint32_t sw = 128u * row + 16u * (uint32_t)(c ^ (row & 7));
            cp_async16(kd + sw, bK + (size_t)row * QKV_N + c * 8);
            cp_async16(vd + sw, bV + (size_t)row * QKV_N + c * 8);
        }
        cp_commit();
    };

    // prologue: Q + K0 + V0 in one group
    {
#pragma unroll
        for (int j = 0; j < 4; j++) {
            const int i   = tid + 128 * j;
            const int row = i >> 3;
            const int c   = i & 7;
            cp_async16(Qb + 128u * row + 16u * (uint32_t)(c ^ (row & 7)),
                       baseQ + (size_t)row * QKV_N + c * 8);
        }
        load_kv(0, 0);
    }

    float m0 = -INFINITY, m1 = -INFINITY;
    float o[9][4];
#pragma unroll
    for (int t = 0; t < 9; t++)
#pragma unroll
        for (int j = 0; j < 4; j++) o[t][j] = 0.f;

    const int mrow0 = w * 16 + grp;                 // first owned S/O row
    const int arow  = w * 16 + (lane & 15);         // ldmatrix A address row
    const int ahi   = lane >> 4;
    const unsigned bone = (lane < 4) ? 0x3C003C00u : 0u;   // ones-column B frag

    unsigned qa[4][4];   // hoisted Q A-fragments (one per 16-wide d chunk)

    for (int kt = 0; kt < FA_TILES; kt++) {
        const int cur = kt & 1;
        __syncthreads();                 // prev compute done reading buf cur^1
        if (kt + 1 < FA_TILES) { load_kv(kt + 1, cur ^ 1); cp_wait1(); }
        else                   { cp_wait0(); }
        __syncthreads();                 // tile kt resident for all warps

        if (kt == 0) {
#pragma unroll
            for (int kc = 0; kc < 4; kc++)
                ldsm_x4(qa[kc], Qb + 128u * arow
                               + 16u * (uint32_t)((kc * 2 + ahi) ^ (arow & 7)));
        }

        const uint32_t Kcur = Kb + (uint32_t)cur * 8192;
        const uint32_t Vcur = Vb + (uint32_t)cur * 8192;

        // ---- S = Q @ K^T (raw scores) ----
        float s[8][4];
#pragma unroll
        for (int nt = 0; nt < 8; nt++)
#pragma unroll
            for (int j = 0; j < 4; j++) s[nt][j] = 0.f;

#pragma unroll
        for (int kc = 0; kc < 4; kc++) {
#pragma unroll
            for (int g = 0; g < 4; g++) {
                unsigned bf[4];
                const int rowb = g * 16 + (lane & 7) + ((lane & 16) ? 8 : 0);
                ldsm_x4(bf, Kcur + 128u * rowb
                             + 16u * (uint32_t)((kc * 2 + ((lane >> 3) & 1)) ^ (rowb & 7)));
                mma_f16(s[2 * g],     qa[kc][0], qa[kc][1], qa[kc][2], qa[kc][3], bf[0], bf[1]);
                mma_f16(s[2 * g + 1], qa[kc][0], qa[kc][1], qa[kc][2], qa[kc][3], bf[2], bf[3]);
            }
        }

        // ---- online softmax (base-2); P -> registers only ----
        float mx0 = -INFINITY, mx1 = -INFINITY;
#pragma unroll
        for (int nt = 0; nt < 8; nt++) {
            mx0 = fmaxf(mx0, fmaxf(s[nt][0], s[nt][1]));
            mx1 = fmaxf(mx1, fmaxf(s[nt][2], s[nt][3]));
        }
        mx0 = fmaxf(mx0, __shfl_xor_sync(0xffffffffu, mx0, 1));
        mx0 = fmaxf(mx0, __shfl_xor_sync(0xffffffffu, mx0, 2));
        mx1 = fmaxf(mx1, __shfl_xor_sync(0xffffffffu, mx1, 1));
        mx1 = fmaxf(mx1, __shfl_xor_sync(0xffffffffu, mx1, 2));

        const float m0n = fmaxf(m0, mx0);
        const float m1n = fmaxf(m1, mx1);
        const float corr0 = exp2f(ALPHA * (m0 - m0n));
        const float corr1 = exp2f(ALPHA * (m1 - m1n));
        m0 = m0n;  m1 = m1n;
        const float na0 = -ALPHA * m0n;
        const float na1 = -ALPHA * m1n;

        unsigned p01[8], p23[8];
#pragma unroll
        for (int nt = 0; nt < 8; nt++) {
            p01[nt] = ex2_f16x2(fmaf(s[nt][0], ALPHA, na0), fmaf(s[nt][1], ALPHA, na0));
            p23[nt] = ex2_f16x2(fmaf(s[nt][2], ALPHA, na1), fmaf(s[nt][3], ALPHA, na1));
        }
#pragma unroll
        for (int t = 0; t < 9; t++) {
            o[t][0] *= corr0;  o[t][1] *= corr0;
            o[t][2] *= corr1;  o[t][3] *= corr1;
        }

        // ---- O += P @ V  (P A-frags direct from registers; ones = l) ----
#pragma unroll
        for (int kc = 0; kc < 4; kc++) {
            const unsigned a0 = p01[2 * kc];
            const unsigned a1 = p23[2 * kc];
            const unsigned a2 = p01[2 * kc + 1];
            const unsigned a3 = p23[2 * kc + 1];
#pragma unroll
            for (int ntp = 0; ntp < 4; ntp++) {
                unsigned bf[4];
                const int rowv = kc * 16 + (lane & 7) + ((lane & 8) ? 8 : 0);
                const int cd   = 2 * ntp + ((lane >> 4) & 1);
                ldsm_x4_t(bf, Vcur + 128u * rowv
                               + 16u * (uint32_t)(cd ^ (rowv & 7)));
                mma_f16(o[2 * ntp],     a0, a1, a2, a3, bf[0], bf[1]);
                mma_f16(o[2 * ntp + 1], a0, a1, a2, a3, bf[2], bf[3]);
            }
            mma_f16(o[8], a0, a1, a2, a3, bone, bone);
        }
    }

    // ---- l from ones column, normalize, write fp16 ----
    const float l0v = __shfl_sync(0xffffffffu, o[8][0], lane & ~3);
    const float l1v = __shfl_sync(0xffffffffu, o[8][2], lane & ~3);
    const float inv0 = 1.f / l0v;
    const float inv1 = 1.f / l1v;

    __half* ob  = outp + (size_t)(b * NSEQ + q0 + mrow0) * DIM + h * HD;
    __half* ob1 = ob + (size_t)8 * DIM;
#pragma unroll
    for (int nt = 0; nt < 8; nt++) {
        const int col = nt * 8 + 2 * q4;
        *(__half2*)&ob[col]  = __floats2half2_rn(o[nt][0] * inv0, o[nt][1] * inv0);
        *(__half2*)&ob1[col] = __floats2half2_rn(o[nt][2] * inv1, o[nt][3] * inv1);
    }
}

// ---------------------------------------------------------------------------
// Launch
// ---------------------------------------------------------------------------
extern "C" void kernel_launch(void* const* d_in, const int* in_sizes, int n_in,
                              void* d_out, int out_size)
{
    const float* x      = (const float*)d_in[0];
    const float* w_qkv  = (const float*)d_in[1];
    const float* b_qkv  = (const float*)d_in[2];
    const float* w_proj = (const float*)d_in[3];
    const float* b_proj = (const float*)d_in[4];
    float* out = (float*)d_out;

    __half *x_h, *qkv_h, *att_h, *wqkv_h, *wproj_h;
    cudaGetSymbolAddress((void**)&x_h,     g_x_h);
    cudaGetSymbolAddress((void**)&qkv_h,   g_qkv_h);
    cudaGetSymbolAddress((void**)&att_h,   g_att_h);
    cudaGetSymbolAddress((void**)&wqkv_h,  g_wqkv_h);
    cudaGetSymbolAddress((void**)&wproj_h, g_wproj_h);

    cudaFuncSetAttribute(hgemm_kernel<true>,
                         cudaFuncAttributeMaxDynamicSharedMemorySize, GEMM_SMEM);
    cudaFuncSetAttribute(hgemm_kernel<false>,
                         cudaFuncAttributeMaxDynamicSharedMemorySize, GEMM_SMEM);
    cudaFuncSetAttribute(flash_f16_kernel,
                         cudaFuncAttributeMaxDynamicSharedMemorySize, FA_SMEM);

    // 0) precision converts + weight transposes
    {
        int n = M_ROWS * DIM;
        f32_to_f16_kernel<<<(n / 4 + 255) / 256, 256>>>(x, x_h, n);
        dim3 blk(32, 8);
        transpose_cvt_kernel<<<dim3(QKV_N / 32, DIM / 32), blk>>>(w_qkv, wqkv_h, DIM, QKV_N);
        transpose_cvt_kernel<<<dim3(DIM / 32, DIM / 32), blk>>>(w_proj, wproj_h, DIM, DIM);
    }

    // 1) QKV projection -> fp16
    {
        dim3 grid(QKV_N / 128, M_ROWS / 128);
        hgemm_kernel<true><<<grid, 256, GEMM_SMEM>>>(x_h, wqkv_h, b_qkv, qkv_h,
                                                     M_ROWS, QKV_N, DIM);
    }

    // 2) Flash attention
    {
        dim3 grid(NSEQ / 64, NHEAD, BATCH);
        flash_f16_kernel<<<grid, 128, FA_SMEM>>>(qkv_h, att_h);
    }

    // 3) Output projection -> fp32
    {
        dim3 grid(DIM / 128, M_ROWS / 128);
        hgemm_kernel<false><<<grid, 256, GEMM_SMEM>>>(att_h, wproj_h, b_proj, out,
                                                      M_ROWS, DIM, DIM);
    }
}